// round 2
// baseline (speedup 1.0000x reference)
#include <cuda_runtime.h>

#define NPTS 100000
#define KOFF 27
#define PL 128
#define VD 16

// ---- scratch (device globals; no allocation) ----
__device__ __align__(16) float g_vf[NPTS * PL];
__device__ __align__(16) float g_agg[NPTS * PL];
__device__ float g_choice[NPTS];
__device__ float g_Wc2[VD * PL];
__device__ float g_C[1];

// ================= prep: fold codebook into W_choice, codebook norm ==========
__global__ void k_prep(const float* __restrict__ cb, const float* __restrict__ Wch) {
    int t = threadIdx.x;
    for (int e = t; e < VD * PL; e += 256) {
        int v = e >> 7, o = e & 127;
        float s = 0.f;
#pragma unroll
        for (int r = 0; r < 8; ++r) s += cb[8 * v + r] * Wch[(8 * v + r) * PL + o];
        g_Wc2[e] = s;
    }
    if (t == 0) {
        float c = 0.f;
        for (int i = 0; i < PL; ++i) c += cb[i] * cb[i];
        g_C[0] = c;
    }
}

// ================= v_f = relu((x@Wv)*g+b) + repeat(coords@Wpos+bpos, 8) ======
// block: 256 threads, 32 points. W_v staged in smem (64KB), broadcast reads.
__global__ void k_vf(const float* __restrict__ x, const float* __restrict__ coords,
                     const float* __restrict__ Wv, const float* __restrict__ vg,
                     const float* __restrict__ vb, const float* __restrict__ Wpos,
                     const float* __restrict__ bpos) {
    extern __shared__ float sm[];
    float* Ws = sm;                 // 16384
    float* xg = sm + 16384;         // 32*129
    float* cg = xg + 32 * 129;      // 96
    int t = threadIdx.x;
    int i0 = blockIdx.x * 32;

    const float4* Wv4 = (const float4*)Wv;
    float4* Ws4 = (float4*)Ws;
    for (int e = t; e < 4096; e += 256) Ws4[e] = Wv4[e];
    for (int e = t; e < 1024; e += 256) {
        int p = e >> 5, c4 = e & 31;
        float4 v = ((const float4*)x)[(size_t)(i0 + p) * 32 + c4];
        float* d = xg + p * 129 + c4 * 4;
        d[0] = v.x; d[1] = v.y; d[2] = v.z; d[3] = v.w;
    }
    if (t < 96) cg[t] = coords[(size_t)i0 * 3 + t];
    __syncthreads();

    int p = t & 31, og = t >> 5;
    float acc[16];
#pragma unroll
    for (int j = 0; j < 16; ++j) acc[j] = 0.f;
    const float* xrow = xg + p * 129;
    for (int c = 0; c < 128; ++c) {
        float xv = xrow[c];
        const float4* wr = (const float4*)(Ws + (c << 7) + (og << 4));
#pragma unroll
        for (int q = 0; q < 4; ++q) {
            float4 w = wr[q];
            acc[4 * q + 0] += xv * w.x; acc[4 * q + 1] += xv * w.y;
            acc[4 * q + 2] += xv * w.z; acc[4 * q + 3] += xv * w.w;
        }
    }
    int i = i0 + p;
    float px = cg[p * 3], py = cg[p * 3 + 1], pz = cg[p * 3 + 2];
    float pos[2];
#pragma unroll
    for (int h = 0; h < 2; ++h) {
        int vch = 2 * og + h;
        pos[h] = px * Wpos[vch] + py * Wpos[16 + vch] + pz * Wpos[32 + vch] + bpos[vch];
    }
#pragma unroll
    for (int j = 0; j < 16; ++j) {
        int o = og * 16 + j;
        float r = acc[j] * vg[o] + vb[o];
        r = fmaxf(r, 0.f) + pos[j >> 3];
        g_vf[(size_t)i * 128 + o] = r;
    }
}

// ================= q conv (masked, compacted) + BN/relu + choice =============
// block: 512 threads, 256 points. Per offset k: compact valid points, gather x
// rows to smem, GEMM [cnt x 128] @ [128 x 16] with W_q[k] transposed in smem.
__global__ void k_q(const float* __restrict__ x, const float* __restrict__ Wq,
                    const float* __restrict__ qg, const float* __restrict__ qb,
                    const float* __restrict__ bch,
                    const int* __restrict__ nidx, const int* __restrict__ nmask) {
    extern __shared__ float sm[];
    float* Wkt  = sm;                  // 16*132 = 2112
    float* xg   = sm + 2112;           // 256*132 = 33792
    float* qacc = xg + 33792;          // 256*16 = 4096
    int*   sl   = (int*)(qacc + 4096); // 256
    int*   sj   = sl + 256;            // 256
    int*   wb   = sj + 256;            // 8

    int t = threadIdx.x;
    int i0 = blockIdx.x * 256;

    for (int e = t; e < 4096; e += 512) qacc[e] = 0.f;

    for (int k = 0; k < KOFF; ++k) {
        __syncthreads();  // previous iteration done with xg/Wkt/sl/sj/wb
        int valid = 0, j = 0;
        if (t < 256) {
            int i = i0 + t;
            if (i < NPTS && nmask[(size_t)k * NPTS + i]) {
                valid = 1; j = nidx[(size_t)k * NPTS + i];
            }
            unsigned b = __ballot_sync(0xffffffffu, valid);
            if ((t & 31) == 0) wb[t >> 5] = (int)b;
        }
        // stage W_q[k] transposed: Wkt[v][c]
        for (int e = t; e < 2048; e += 512) {
            int c = e >> 4, v = e & 15;
            Wkt[v * 132 + c] = Wq[(size_t)k * 2048 + e];
        }
        __syncthreads();
        if (t < 256 && valid) {
            int w = t >> 5;
            int base = 0;
            for (int q = 0; q < w; ++q) base += __popc((unsigned)wb[q]);
            base += __popc(((unsigned)wb[w]) & ((1u << (t & 31)) - 1u));
            sl[base] = t; sj[base] = j;
        }
        int cnt = 0;
#pragma unroll
        for (int q = 0; q < 8; ++q) cnt += __popc((unsigned)wb[q]);
        __syncthreads();
        // gather valid rows into smem
        int wid = t >> 5, lane = t & 31;
        for (int s = wid; s < cnt; s += 16) {
            int jj = sj[s];
            float4 v = ((const float4*)x)[(size_t)jj * 32 + lane];
            ((float4*)(xg + s * 132))[lane] = v;
        }
        __syncthreads();
        // compute: work item = (slot, v2) -> 2 output channels, full c
        for (int wk = t; wk < cnt * 8; wk += 512) {
            int slot = wk >> 3, v2 = wk & 7;
            const float4* xr = (const float4*)(xg + slot * 132);
            const float4* w0 = (const float4*)(Wkt + (2 * v2) * 132);
            const float4* w1 = (const float4*)(Wkt + (2 * v2 + 1) * 132);
            float a00 = 0, a01 = 0, a02 = 0, a03 = 0;
            float a10 = 0, a11 = 0, a12 = 0, a13 = 0;
#pragma unroll
            for (int c4 = 0; c4 < 32; ++c4) {
                float4 xv = xr[c4], u = w0[c4], w = w1[c4];
                a00 += xv.x * u.x; a01 += xv.y * u.y; a02 += xv.z * u.z; a03 += xv.w * u.w;
                a10 += xv.x * w.x; a11 += xv.y * w.y; a12 += xv.z * w.z; a13 += xv.w * w.w;
            }
            int p = sl[slot];
            qacc[p * 16 + 2 * v2]     += (a00 + a01) + (a02 + a03);
            qacc[p * 16 + 2 * v2 + 1] += (a10 + a11) + (a12 + a13);
        }
    }
    __syncthreads();
    // q_f = relu(q_pre * gamma + beta)  (in place)
    for (int e = t; e < 4096; e += 512) {
        int v = e & 15;
        qacc[e] = fmaxf(qacc[e] * qg[v] + qb[v], 0.f);
    }
    __syncthreads();
    // choice[i] = sum_o relu(q_f . Wc2[:,o] + b_choice[o])
    {
        int p = t >> 1, half = t & 1;
        int i = i0 + p;
        float qf[16];
#pragma unroll
        for (int v = 0; v < 16; ++v) qf[v] = qacc[p * 16 + v];
        float ssum = 0.f;
        for (int o = half * 64; o < half * 64 + 64; ++o) {
            float s = bch[o];
#pragma unroll
            for (int v = 0; v < 16; ++v) s += qf[v] * g_Wc2[v * 128 + o];
            ssum += fmaxf(s, 0.f);
        }
        ssum += __shfl_xor_sync(0xffffffffu, ssum, 1);
        if (half == 0 && i < NPTS) g_choice[i] = ssum;
    }
}

// ================= attention (rank-1 scores) + weighted aggregation ==========
// one warp per point
__global__ void k_attn(const int* __restrict__ nidx, const int* __restrict__ nmask) {
    int lane = threadIdx.x & 31;
    int wid = threadIdx.x >> 5;
    int i = blockIdx.x * 8 + wid;
    if (i >= NPTS) return;
    float tC = g_C[0] * g_choice[i];
    int m = 0, j = 0;
    float s = -1e9f;
    if (lane < KOFF) {
        m = nmask[(size_t)lane * NPTS + i];
        j = nidx[(size_t)lane * NPTS + i];
        s = m ? tC * g_choice[j] : -1e9f;
    }
    float mx = s;
#pragma unroll
    for (int d = 16; d; d >>= 1) mx = fmaxf(mx, __shfl_xor_sync(0xffffffffu, mx, d));
    float e = (lane < KOFF && m) ? expf(s - mx) : 0.f;
    float se = e;
#pragma unroll
    for (int d = 16; d; d >>= 1) se += __shfl_xor_sync(0xffffffffu, se, d);
    float a = e / se;

    float4 acc = {0.f, 0.f, 0.f, 0.f};
    for (int k = 0; k < KOFF; ++k) {
        float ak = __shfl_sync(0xffffffffu, a, k);
        int   jk = __shfl_sync(0xffffffffu, j, k);
        int   mk = __shfl_sync(0xffffffffu, m, k);
        if (mk) {
            float4 v = ((const float4*)g_vf)[(size_t)jk * 32 + lane];
            acc.x += ak * v.x; acc.y += ak * v.y; acc.z += ak * v.z; acc.w += ak * v.w;
        }
    }
    ((float4*)g_agg)[(size_t)i * 32 + lane] = acc;
}

// ================= out = relu((agg@Wo)*g+b) + x ==============================
__global__ void k_out(const float* __restrict__ x, const float* __restrict__ Wo,
                      const float* __restrict__ ogm, const float* __restrict__ obt,
                      float* __restrict__ out) {
    extern __shared__ float sm[];
    float* Ws = sm;             // 16384
    float* ag = sm + 16384;     // 32*129
    int t = threadIdx.x;
    int i0 = blockIdx.x * 32;

    const float4* Wo4 = (const float4*)Wo;
    float4* Ws4 = (float4*)Ws;
    for (int e = t; e < 4096; e += 256) Ws4[e] = Wo4[e];
    for (int e = t; e < 1024; e += 256) {
        int p = e >> 5, c4 = e & 31;
        float4 v = ((const float4*)g_agg)[(size_t)(i0 + p) * 32 + c4];
        float* d = ag + p * 129 + c4 * 4;
        d[0] = v.x; d[1] = v.y; d[2] = v.z; d[3] = v.w;
    }
    __syncthreads();

    int p = t & 31, ogr = t >> 5;
    float acc[16];
#pragma unroll
    for (int j = 0; j < 16; ++j) acc[j] = 0.f;
    const float* arow = ag + p * 129;
    for (int c = 0; c < 128; ++c) {
        float xv = arow[c];
        const float4* wr = (const float4*)(Ws + (c << 7) + (ogr << 4));
#pragma unroll
        for (int q = 0; q < 4; ++q) {
            float4 w = wr[q];
            acc[4 * q + 0] += xv * w.x; acc[4 * q + 1] += xv * w.y;
            acc[4 * q + 2] += xv * w.z; acc[4 * q + 3] += xv * w.w;
        }
    }
    int i = i0 + p;
    const float4* x4 = (const float4*)(x + (size_t)i * 128 + ogr * 16);
    float4* o4 = (float4*)(out + (size_t)i * 128 + ogr * 16);
#pragma unroll
    for (int q = 0; q < 4; ++q) {
        float4 xr = x4[q];
        float4 r;
        int o = ogr * 16 + 4 * q;
        r.x = fmaxf(acc[4 * q + 0] * ogm[o + 0] + obt[o + 0], 0.f) + xr.x;
        r.y = fmaxf(acc[4 * q + 1] * ogm[o + 1] + obt[o + 1], 0.f) + xr.y;
        r.z = fmaxf(acc[4 * q + 2] * ogm[o + 2] + obt[o + 2], 0.f) + xr.z;
        r.w = fmaxf(acc[4 * q + 3] * ogm[o + 3] + obt[o + 3], 0.f) + xr.w;
        o4[q] = r;
    }
}

// ================= launch ====================================================
extern "C" void kernel_launch(void* const* d_in, const int* in_sizes, int n_in,
                              void* d_out, int out_size) {
    const float* x      = (const float*)d_in[0];
    const float* coords = (const float*)d_in[1];
    const float* Wq     = (const float*)d_in[2];
    const float* qg     = (const float*)d_in[3];
    const float* qb     = (const float*)d_in[4];
    const float* Wv     = (const float*)d_in[5];
    const float* vg     = (const float*)d_in[6];
    const float* vb     = (const float*)d_in[7];
    const float* cb     = (const float*)d_in[8];
    const float* Wch    = (const float*)d_in[9];
    const float* bch    = (const float*)d_in[10];
    const float* Wpos   = (const float*)d_in[11];
    const float* bpos   = (const float*)d_in[12];
    const float* Wo     = (const float*)d_in[13];
    const float* ogm    = (const float*)d_in[14];
    const float* obt    = (const float*)d_in[15];
    const int*   nidx   = (const int*)d_in[16];
    const int*   nmask  = (const int*)d_in[17];
    float* out = (float*)d_out;

    size_t smem_vf  = (size_t)(16384 + 32 * 129 + 96) * 4;
    size_t smem_q   = (size_t)(2112 + 33792 + 4096) * 4 + (256 + 256 + 8) * 4;
    size_t smem_out = (size_t)(16384 + 32 * 129) * 4;
    cudaFuncSetAttribute(k_vf,  cudaFuncAttributeMaxDynamicSharedMemorySize, (int)smem_vf);
    cudaFuncSetAttribute(k_q,   cudaFuncAttributeMaxDynamicSharedMemorySize, (int)smem_q);
    cudaFuncSetAttribute(k_out, cudaFuncAttributeMaxDynamicSharedMemorySize, (int)smem_out);

    k_prep<<<1, 256>>>(cb, Wch);
    k_vf<<<NPTS / 32, 256, smem_vf>>>(x, coords, Wv, vg, vb, Wpos, bpos);
    k_q<<<(NPTS + 255) / 256, 512, smem_q>>>(x, Wq, qg, qb, bch, nidx, nmask);
    k_attn<<<(NPTS + 7) / 8, 256>>>(nidx, nmask);
    k_out<<<NPTS / 32, 256, smem_out>>>(x, Wo, ogm, obt, out);
}

// round 5
// speedup vs baseline: 1.7458x; 1.7458x over previous
#include <cuda_runtime.h>

#define NPTS 100000
#define KOFF 27
#define PL 128
#define VD 16
#define NQ 432   // 27*16
#define XPITCH 132  // floats; row base = c*528 bytes -> 16B aligned, mod-4 pitch

// ---- scratch (device globals; no allocation) ----
__device__ __align__(16) float g_Y[(size_t)NPTS * NQ];
__device__ __align__(16) float g_vf[(size_t)NPTS * PL];
__device__ __align__(16) float g_agg[(size_t)NPTS * PL];
__device__ float g_choice[NPTS];
__device__ __align__(16) float g_Wc2[VD * PL];
__device__ __align__(16) float g_Wcat[PL * NQ];
__device__ float g_C[1];

// ---- packed f32x2 helpers (FFMA2 path) ----
__device__ __forceinline__ unsigned long long pk2(float lo, float hi) {
    unsigned long long r;
    asm("mov.b64 %0, {%1,%2};" : "=l"(r) : "f"(lo), "f"(hi));
    return r;
}
__device__ __forceinline__ void fma2(unsigned long long& c, unsigned long long a,
                                     unsigned long long b) {
    asm("fma.rn.f32x2 %0, %1, %2, %0;" : "+l"(c) : "l"(a), "l"(b));
}
__device__ __forceinline__ float2 upk2(unsigned long long v) {
    float2 r;
    asm("mov.b64 {%0,%1}, %2;" : "=f"(r.x), "=f"(r.y) : "l"(v));
    return r;
}

// ================= prep =====================================================
// blocks 0..26: Wcat[c][k*16+v] = Wq[k][c][v];  block 27: Wc2 fold + C
__global__ void k_prep(const float* __restrict__ cb, const float* __restrict__ Wch,
                       const float* __restrict__ Wq) {
    int b = blockIdx.x, t = threadIdx.x;
    if (b < KOFF) {
        for (int e = t; e < 2048; e += 256) {
            int c = e >> 4, v = e & 15;
            g_Wcat[(size_t)c * NQ + b * 16 + v] = Wq[(size_t)b * 2048 + e];
        }
    } else {
        for (int e = t; e < VD * PL; e += 256) {
            int v = e >> 7, o = e & 127;
            float s = 0.f;
#pragma unroll
            for (int r = 0; r < 8; ++r) s += cb[8 * v + r] * Wch[(8 * v + r) * PL + o];
            g_Wc2[e] = s;
        }
        if (t == 0) {
            float c = 0.f;
            for (int i = 0; i < PL; ++i) c += cb[i] * cb[i];
            g_C[0] = c;
        }
    }
}

// ================= register-tiled FFMA2 GEMM ================================
// C[BM=128, BN=NG*8] tile; threads = 16*NG; thread: mg=t&15 (8 rows), ng=t>>4 (8 cols)
// MODE 0: plain store (Y). MODE 1: BN+relu+pos (v_f). MODE 2: BN+relu+residual (out)
template <int NG, int MODE>
__global__ void k_gemm(const float* __restrict__ A, const float* __restrict__ Wsrc,
                       float* __restrict__ Out, int Npitch, int nch,
                       const float* __restrict__ g1, const float* __restrict__ b1,
                       const float* __restrict__ coords, const float* __restrict__ Wpos,
                       const float* __restrict__ bpos, const float* __restrict__ resid) {
    constexpr int BN = NG * 8;
    constexpr int T = 16 * NG;
    extern __shared__ float sm[];
    float* xg = sm;                    // [128 c][XPITCH] transposed x tile
    float* wg = sm + 128 * XPITCH;     // [128 c][BN]
    int t = threadIdx.x;
    int i0 = blockIdx.x * 128;
    int mg = t & 15, ng = t >> 4;

    // load x tile transposed (scalar stores, any pitch OK)
    for (int e = t; e < 4096; e += T) {
        int ml = e & 7, c4 = (e >> 3) & 31, mb = e >> 8;
        int m = mb * 8 + ml;
        int gi = i0 + m;
        float4 v = (gi < NPTS) ? ((const float4*)A)[(size_t)gi * 32 + c4]
                               : make_float4(0.f, 0.f, 0.f, 0.f);
        int cc = c4 * 4;
        xg[(cc + 0) * XPITCH + m] = v.x; xg[(cc + 1) * XPITCH + m] = v.y;
        xg[(cc + 2) * XPITCH + m] = v.z; xg[(cc + 3) * XPITCH + m] = v.w;
    }

    for (int ch = 0; ch < nch; ++ch) {
        int n0 = ch * BN;
        __syncthreads();
        for (int e = t; e < 128 * (BN / 4); e += T) {
            int c = e / (BN / 4), n4 = e % (BN / 4);
            ((float4*)wg)[c * (BN / 4) + n4] =
                ((const float4*)Wsrc)[(size_t)c * (Npitch / 4) + n0 / 4 + n4];
        }
        __syncthreads();

        unsigned long long acc[32];
#pragma unroll
        for (int q = 0; q < 32; ++q) acc[q] = 0ull;

#pragma unroll 4
        for (int c = 0; c < 128; ++c) {
            const float4* xp = (const float4*)(xg + c * XPITCH + mg * 8);  // 16B aligned
            float4 xa = xp[0], xb = xp[1];
            const float4* wp = (const float4*)(wg + c * BN + ng * 8);
            float4 wa = wp[0], wb = wp[1];
            unsigned long long xk0 = pk2(xa.x, xa.y), xk1 = pk2(xa.z, xa.w);
            unsigned long long xk2 = pk2(xb.x, xb.y), xk3 = pk2(xb.z, xb.w);
            float wv[8] = {wa.x, wa.y, wa.z, wa.w, wb.x, wb.y, wb.z, wb.w};
#pragma unroll
            for (int j = 0; j < 8; ++j) {
                unsigned long long wd = pk2(wv[j], wv[j]);
                fma2(acc[0 * 8 + j], xk0, wd);
                fma2(acc[1 * 8 + j], xk1, wd);
                fma2(acc[2 * 8 + j], xk2, wd);
                fma2(acc[3 * 8 + j], xk3, wd);
            }
        }

        // epilogue
        float ga[8], bb[8];
        if (MODE != 0) {
#pragma unroll
            for (int j = 0; j < 8; ++j) { ga[j] = g1[ng * 8 + j]; bb[j] = b1[ng * 8 + j]; }
        }
#pragma unroll
        for (int i2 = 0; i2 < 4; ++i2) {
#pragma unroll
            for (int p = 0; p < 2; ++p) {
                int m = mg * 8 + i2 * 2 + p;
                int gi = i0 + m;
                if (gi >= NPTS) continue;
                float v[8];
#pragma unroll
                for (int j = 0; j < 8; ++j) {
                    float2 u = upk2(acc[i2 * 8 + j]);
                    v[j] = p ? u.y : u.x;
                }
                if (MODE == 0) {
                    float4* o4 = (float4*)(Out + (size_t)gi * Npitch + n0 + ng * 8);
                    o4[0] = make_float4(v[0], v[1], v[2], v[3]);
                    o4[1] = make_float4(v[4], v[5], v[6], v[7]);
                } else if (MODE == 1) {
                    float cx = coords[(size_t)gi * 3], cy = coords[(size_t)gi * 3 + 1],
                          cz = coords[(size_t)gi * 3 + 2];
                    float pos = cx * Wpos[ng] + cy * Wpos[16 + ng] + cz * Wpos[32 + ng] + bpos[ng];
#pragma unroll
                    for (int j = 0; j < 8; ++j) v[j] = fmaxf(v[j] * ga[j] + bb[j], 0.f) + pos;
                    float4* o4 = (float4*)(Out + (size_t)gi * 128 + ng * 8);
                    o4[0] = make_float4(v[0], v[1], v[2], v[3]);
                    o4[1] = make_float4(v[4], v[5], v[6], v[7]);
                } else {
                    const float4* r4 = (const float4*)(resid + (size_t)gi * 128 + ng * 8);
                    float4 ra = r4[0], rb = r4[1];
                    float rr[8] = {ra.x, ra.y, ra.z, ra.w, rb.x, rb.y, rb.z, rb.w};
#pragma unroll
                    for (int j = 0; j < 8; ++j) v[j] = fmaxf(v[j] * ga[j] + bb[j], 0.f) + rr[j];
                    float4* o4 = (float4*)(Out + (size_t)gi * 128 + ng * 8);
                    o4[0] = make_float4(v[0], v[1], v[2], v[3]);
                    o4[1] = make_float4(v[4], v[5], v[6], v[7]);
                }
            }
        }
    }
}

// ================= masked gather of Y + BN/relu + choice ====================
// one warp per point
__global__ void k_qg(const int* __restrict__ nidx, const int* __restrict__ nmask,
                     const float* __restrict__ qg, const float* __restrict__ qb,
                     const float* __restrict__ bch) {
    __shared__ float wc[2048];
    __shared__ float bs[128];
    int t = threadIdx.x;
    for (int e = t; e < 2048; e += 256) wc[e] = g_Wc2[e];
    for (int e = t; e < 128; e += 256) bs[e] = bch[e];
    __syncthreads();
    int lane = t & 31, w = t >> 5;
    int i = blockIdx.x * 8 + w;
    if (i >= NPTS) return;
    int v = lane & 15, h = lane >> 4;

    float qp = 0.f;
    for (int k = h; k < KOFF; k += 2) {
        if (nmask[(size_t)k * NPTS + i]) {
            int j = nidx[(size_t)k * NPTS + i];
            qp += g_Y[(size_t)j * NQ + k * 16 + v];
        }
    }
    qp += __shfl_xor_sync(0xffffffffu, qp, 16);
    float qf = fmaxf(qp * qg[v] + qb[v], 0.f);
    float qa[16];
#pragma unroll
    for (int vv = 0; vv < 16; ++vv) qa[vv] = __shfl_sync(0xffffffffu, qf, vv);

    // choice: lane handles 4 consecutive outputs via float4 smem reads (conflict-free)
    float4 av = ((const float4*)bs)[lane];
#pragma unroll
    for (int vv = 0; vv < 16; ++vv) {
        float4 wv4 = *(const float4*)(wc + vv * 128 + lane * 4);
        av.x += qa[vv] * wv4.x; av.y += qa[vv] * wv4.y;
        av.z += qa[vv] * wv4.z; av.w += qa[vv] * wv4.w;
    }
    float s = fmaxf(av.x, 0.f) + fmaxf(av.y, 0.f) + fmaxf(av.z, 0.f) + fmaxf(av.w, 0.f);
#pragma unroll
    for (int d = 16; d; d >>= 1) s += __shfl_xor_sync(0xffffffffu, s, d);
    if (lane == 0) g_choice[i] = s;
}

// ================= attention (rank-1 scores) + weighted aggregation ==========
__global__ void k_attn(const int* __restrict__ nidx, const int* __restrict__ nmask) {
    int lane = threadIdx.x & 31;
    int wid = threadIdx.x >> 5;
    int i = blockIdx.x * 8 + wid;
    if (i >= NPTS) return;
    float tC = g_C[0] * g_choice[i];
    int m = 0, j = 0;
    float s = -1e9f;
    if (lane < KOFF) {
        m = nmask[(size_t)lane * NPTS + i];
        j = nidx[(size_t)lane * NPTS + i];
        s = m ? tC * g_choice[j] : -1e9f;
    }
    float mx = s;
#pragma unroll
    for (int d = 16; d; d >>= 1) mx = fmaxf(mx, __shfl_xor_sync(0xffffffffu, mx, d));
    float e = (lane < KOFF && m) ? expf(s - mx) : 0.f;
    float se = e;
#pragma unroll
    for (int d = 16; d; d >>= 1) se += __shfl_xor_sync(0xffffffffu, se, d);
    float a = e / se;

    float4 acc = {0.f, 0.f, 0.f, 0.f};
    for (int k = 0; k < KOFF; ++k) {
        float ak = __shfl_sync(0xffffffffu, a, k);
        int jk = __shfl_sync(0xffffffffu, j, k);
        int mk = __shfl_sync(0xffffffffu, m, k);
        if (mk) {
            float4 v = ((const float4*)g_vf)[(size_t)jk * 32 + lane];
            acc.x += ak * v.x; acc.y += ak * v.y; acc.z += ak * v.z; acc.w += ak * v.w;
        }
    }
    ((float4*)g_agg)[(size_t)i * 32 + lane] = acc;
}

// ================= launch ====================================================
extern "C" void kernel_launch(void* const* d_in, const int* in_sizes, int n_in,
                              void* d_out, int out_size) {
    const float* x      = (const float*)d_in[0];
    const float* coords = (const float*)d_in[1];
    const float* Wq     = (const float*)d_in[2];
    const float* qg     = (const float*)d_in[3];
    const float* qb     = (const float*)d_in[4];
    const float* Wv     = (const float*)d_in[5];
    const float* vg     = (const float*)d_in[6];
    const float* vb     = (const float*)d_in[7];
    const float* cb     = (const float*)d_in[8];
    const float* Wch    = (const float*)d_in[9];
    const float* bch    = (const float*)d_in[10];
    const float* Wpos   = (const float*)d_in[11];
    const float* bpos   = (const float*)d_in[12];
    const float* Wo     = (const float*)d_in[13];
    const float* ogm    = (const float*)d_in[14];
    const float* obt    = (const float*)d_in[15];
    const int*   nidx   = (const int*)d_in[16];
    const int*   nmask  = (const int*)d_in[17];
    float* out = (float*)d_out;

    float *Y, *vf, *agg, *Wcat;
    cudaGetSymbolAddress((void**)&Y, g_Y);
    cudaGetSymbolAddress((void**)&vf, g_vf);
    cudaGetSymbolAddress((void**)&agg, g_agg);
    cudaGetSymbolAddress((void**)&Wcat, g_Wcat);

    size_t smY = (size_t)(128 * XPITCH + 128 * 144) * 4;  // 141312
    size_t smG = (size_t)(128 * XPITCH + 128 * 128) * 4;  // 133120
    cudaFuncSetAttribute(k_gemm<18, 0>, cudaFuncAttributeMaxDynamicSharedMemorySize, (int)smY);
    cudaFuncSetAttribute(k_gemm<16, 1>, cudaFuncAttributeMaxDynamicSharedMemorySize, (int)smG);
    cudaFuncSetAttribute(k_gemm<16, 2>, cudaFuncAttributeMaxDynamicSharedMemorySize, (int)smG);

    int mblocks = (NPTS + 127) / 128;  // 782

    k_prep<<<KOFF + 1, 256>>>(cb, Wch, Wq);
    // Y = x @ Wcat  [100000 x 432], 3 chunks of 144
    k_gemm<18, 0><<<mblocks, 288, smY>>>(x, Wcat, Y, NQ, 3,
                                         nullptr, nullptr, nullptr, nullptr, nullptr, nullptr);
    // v_f = relu((x@Wv)*g+b) + pos
    k_gemm<16, 1><<<mblocks, 256, smG>>>(x, Wv, vf, PL, 1,
                                         vg, vb, coords, Wpos, bpos, nullptr);
    // q gather + choice
    k_qg<<<(NPTS + 7) / 8, 256>>>(nidx, nmask, qg, qb, bch);
    // attention + aggregation
    k_attn<<<(NPTS + 7) / 8, 256>>>(nidx, nmask);
    // out = relu((agg@Wo)*g+b) + x
    k_gemm<16, 2><<<mblocks, 256, smG>>>(agg, Wo, out, PL, 1,
                                         ogm, obt, nullptr, nullptr, nullptr, x);
}

// round 6
// speedup vs baseline: 1.9413x; 1.1120x over previous
#include <cuda_runtime.h>

#define NPTS 100000
#define KOFF 27
#define PL 128
#define VD 16
#define NQ 432      // 27*16
#define XPITCH 132  // floats; row base = c*528 bytes -> 16B aligned

// ---- scratch (device globals; no allocation) ----
__device__ __align__(16) float g_Y[(size_t)NPTS * NQ];
__device__ __align__(16) float g_vf[(size_t)NPTS * PL];
__device__ __align__(16) float g_agg[(size_t)NPTS * PL];
__device__ float g_choice[NPTS];
__device__ __align__(16) float g_Wc2[VD * PL];
__device__ __align__(16) float g_Wcat[PL * NQ];
__device__ float g_C[1];

// ---- packed f32x2 helpers (FFMA2 path) ----
__device__ __forceinline__ unsigned long long pk2(float lo, float hi) {
    unsigned long long r;
    asm("mov.b64 %0, {%1,%2};" : "=l"(r) : "f"(lo), "f"(hi));
    return r;
}
__device__ __forceinline__ void fma2(unsigned long long& c, unsigned long long a,
                                     unsigned long long b) {
    asm("fma.rn.f32x2 %0, %1, %2, %0;" : "+l"(c) : "l"(a), "l"(b));
}
__device__ __forceinline__ float2 upk2(unsigned long long v) {
    float2 r;
    asm("mov.b64 {%0,%1}, %2;" : "=f"(r.x), "=f"(r.y) : "l"(v));
    return r;
}

// ================= prep =====================================================
__global__ void k_prep(const float* __restrict__ cb, const float* __restrict__ Wch,
                       const float* __restrict__ Wq) {
    int b = blockIdx.x, t = threadIdx.x;
    if (b < KOFF) {
        for (int e = t; e < 2048; e += 256) {
            int c = e >> 4, v = e & 15;
            g_Wcat[(size_t)c * NQ + b * 16 + v] = Wq[(size_t)b * 2048 + e];
        }
    } else {
        for (int e = t; e < VD * PL; e += 256) {
            int v = e >> 7, o = e & 127;
            float s = 0.f;
#pragma unroll
            for (int r = 0; r < 8; ++r) s += cb[8 * v + r] * Wch[(8 * v + r) * PL + o];
            g_Wc2[e] = s;
        }
        if (t == 0) {
            float c = 0.f;
            for (int i = 0; i < PL; ++i) c += cb[i] * cb[i];
            g_C[0] = c;
        }
    }
}

// ================= fused Y + v_f GEMM =======================================
// BM=128, BN=144, 288 threads. Chunks 0..2: Y = x@Wcat (plain store).
// Chunk 3: v_f = relu((x@Wv)*g+b)+pos  (only ng<16 active; BN eff = 128).
__global__ void k_gemmYV(const float* __restrict__ A, const float* __restrict__ Wv,
                         const float* __restrict__ g1, const float* __restrict__ b1,
                         const float* __restrict__ coords, const float* __restrict__ Wpos,
                         const float* __restrict__ bpos) {
    constexpr int BN = 144;
    constexpr int T = 288;
    extern __shared__ float sm[];
    float* xg = sm;                  // [128][XPITCH]
    float* wg = sm + 128 * XPITCH;   // [128][144]
    int t = threadIdx.x;
    int i0 = blockIdx.x * 128;
    int mg = t & 15, ng = t >> 4;

    for (int e = t; e < 4096; e += T) {
        int ml = e & 7, c4 = (e >> 3) & 31, mb = e >> 8;
        int m = mb * 8 + ml;
        int gi = i0 + m;
        float4 v = (gi < NPTS) ? ((const float4*)A)[(size_t)gi * 32 + c4]
                               : make_float4(0.f, 0.f, 0.f, 0.f);
        int cc = c4 * 4;
        xg[(cc + 0) * XPITCH + m] = v.x; xg[(cc + 1) * XPITCH + m] = v.y;
        xg[(cc + 2) * XPITCH + m] = v.z; xg[(cc + 3) * XPITCH + m] = v.w;
    }

    for (int ch = 0; ch < 4; ++ch) {
        __syncthreads();
        if (ch < 3) {
            int n0 = ch * BN;
            for (int e = t; e < 128 * 36; e += T) {
                int c = e / 36, n4 = e % 36;
                ((float4*)wg)[c * 36 + n4] =
                    ((const float4*)g_Wcat)[(size_t)c * (NQ / 4) + n0 / 4 + n4];
            }
        } else {
            for (int e = t; e < 128 * 32; e += T) {
                int c = e >> 5, n4 = e & 31;
                ((float4*)wg)[c * 36 + n4] = ((const float4*)Wv)[(size_t)c * 32 + n4];
            }
        }
        __syncthreads();

        unsigned long long acc[32];
#pragma unroll
        for (int q = 0; q < 32; ++q) acc[q] = 0ull;

#pragma unroll 4
        for (int c = 0; c < 128; ++c) {
            const float4* xp = (const float4*)(xg + c * XPITCH + mg * 8);
            float4 xa = xp[0], xb = xp[1];
            const float4* wp = (const float4*)(wg + c * BN + (ng < 18 ? ng : 0) * 8);
            float4 wa = wp[0], wb = wp[1];
            unsigned long long xk0 = pk2(xa.x, xa.y), xk1 = pk2(xa.z, xa.w);
            unsigned long long xk2 = pk2(xb.x, xb.y), xk3 = pk2(xb.z, xb.w);
            float wv[8] = {wa.x, wa.y, wa.z, wa.w, wb.x, wb.y, wb.z, wb.w};
#pragma unroll
            for (int j = 0; j < 8; ++j) {
                unsigned long long wd = pk2(wv[j], wv[j]);
                fma2(acc[0 * 8 + j], xk0, wd);
                fma2(acc[1 * 8 + j], xk1, wd);
                fma2(acc[2 * 8 + j], xk2, wd);
                fma2(acc[3 * 8 + j], xk3, wd);
            }
        }

        if (ch < 3) {
            int n0 = ch * BN;
#pragma unroll
            for (int i2 = 0; i2 < 4; ++i2) {
#pragma unroll
                for (int p = 0; p < 2; ++p) {
                    int gi = i0 + mg * 8 + i2 * 2 + p;
                    if (gi >= NPTS) continue;
                    float v[8];
#pragma unroll
                    for (int j = 0; j < 8; ++j) {
                        float2 u = upk2(acc[i2 * 8 + j]);
                        v[j] = p ? u.y : u.x;
                    }
                    float4* o4 = (float4*)(g_Y + (size_t)gi * NQ + n0 + ng * 8);
                    o4[0] = make_float4(v[0], v[1], v[2], v[3]);
                    o4[1] = make_float4(v[4], v[5], v[6], v[7]);
                }
            }
        } else if (ng < 16) {
            float ga[8], bb[8];
#pragma unroll
            for (int j = 0; j < 8; ++j) { ga[j] = g1[ng * 8 + j]; bb[j] = b1[ng * 8 + j]; }
            float wp0 = Wpos[ng], wp1 = Wpos[16 + ng], wp2 = Wpos[32 + ng], bp = bpos[ng];
#pragma unroll
            for (int i2 = 0; i2 < 4; ++i2) {
#pragma unroll
                for (int p = 0; p < 2; ++p) {
                    int gi = i0 + mg * 8 + i2 * 2 + p;
                    if (gi >= NPTS) continue;
                    float cx = coords[(size_t)gi * 3], cy = coords[(size_t)gi * 3 + 1],
                          cz = coords[(size_t)gi * 3 + 2];
                    float pos = cx * wp0 + cy * wp1 + cz * wp2 + bp;
                    float v[8];
#pragma unroll
                    for (int j = 0; j < 8; ++j) {
                        float2 u = upk2(acc[i2 * 8 + j]);
                        v[j] = fmaxf((p ? u.y : u.x) * ga[j] + bb[j], 0.f) + pos;
                    }
                    float4* o4 = (float4*)(g_vf + (size_t)gi * 128 + ng * 8);
                    o4[0] = make_float4(v[0], v[1], v[2], v[3]);
                    o4[1] = make_float4(v[4], v[5], v[6], v[7]);
                }
            }
        }
    }
}

// ================= out GEMM: relu((agg@Wo)*g+b) + x =========================
__global__ void k_gemmO(const float* __restrict__ Wo, const float* __restrict__ g1,
                        const float* __restrict__ b1, const float* __restrict__ resid,
                        float* __restrict__ Out) {
    constexpr int BN = 128;
    constexpr int T = 256;
    extern __shared__ float sm[];
    float* xg = sm;
    float* wg = sm + 128 * XPITCH;
    int t = threadIdx.x;
    int i0 = blockIdx.x * 128;
    int mg = t & 15, ng = t >> 4;

    for (int e = t; e < 4096; e += T) {
        int ml = e & 7, c4 = (e >> 3) & 31, mb = e >> 8;
        int m = mb * 8 + ml;
        int gi = i0 + m;
        float4 v = (gi < NPTS) ? ((const float4*)g_agg)[(size_t)gi * 32 + c4]
                               : make_float4(0.f, 0.f, 0.f, 0.f);
        int cc = c4 * 4;
        xg[(cc + 0) * XPITCH + m] = v.x; xg[(cc + 1) * XPITCH + m] = v.y;
        xg[(cc + 2) * XPITCH + m] = v.z; xg[(cc + 3) * XPITCH + m] = v.w;
    }
    for (int e = t; e < 128 * 32; e += T)
        ((float4*)wg)[e] = ((const float4*)Wo)[e];
    __syncthreads();

    unsigned long long acc[32];
#pragma unroll
    for (int q = 0; q < 32; ++q) acc[q] = 0ull;

#pragma unroll 4
    for (int c = 0; c < 128; ++c) {
        const float4* xp = (const float4*)(xg + c * XPITCH + mg * 8);
        float4 xa = xp[0], xb = xp[1];
        const float4* wp = (const float4*)(wg + c * BN + ng * 8);
        float4 wa = wp[0], wb = wp[1];
        unsigned long long xk0 = pk2(xa.x, xa.y), xk1 = pk2(xa.z, xa.w);
        unsigned long long xk2 = pk2(xb.x, xb.y), xk3 = pk2(xb.z, xb.w);
        float wv[8] = {wa.x, wa.y, wa.z, wa.w, wb.x, wb.y, wb.z, wb.w};
#pragma unroll
        for (int j = 0; j < 8; ++j) {
            unsigned long long wd = pk2(wv[j], wv[j]);
            fma2(acc[0 * 8 + j], xk0, wd);
            fma2(acc[1 * 8 + j], xk1, wd);
            fma2(acc[2 * 8 + j], xk2, wd);
            fma2(acc[3 * 8 + j], xk3, wd);
        }
    }

    float ga[8], bb[8];
#pragma unroll
    for (int j = 0; j < 8; ++j) { ga[j] = g1[ng * 8 + j]; bb[j] = b1[ng * 8 + j]; }
#pragma unroll
    for (int i2 = 0; i2 < 4; ++i2) {
#pragma unroll
        for (int p = 0; p < 2; ++p) {
            int gi = i0 + mg * 8 + i2 * 2 + p;
            if (gi >= NPTS) continue;
            const float4* r4 = (const float4*)(resid + (size_t)gi * 128 + ng * 8);
            float4 ra = r4[0], rb = r4[1];
            float rr[8] = {ra.x, ra.y, ra.z, ra.w, rb.x, rb.y, rb.z, rb.w};
            float v[8];
#pragma unroll
            for (int j = 0; j < 8; ++j) {
                float2 u = upk2(acc[i2 * 8 + j]);
                v[j] = fmaxf((p ? u.y : u.x) * ga[j] + bb[j], 0.f) + rr[j];
            }
            float4* o4 = (float4*)(Out + (size_t)gi * 128 + ng * 8);
            o4[0] = make_float4(v[0], v[1], v[2], v[3]);
            o4[1] = make_float4(v[4], v[5], v[6], v[7]);
        }
    }
}

// ================= masked gather of Y + BN/relu + choice ====================
// one warp per point; branch-free unrolled gathers for MLP
__global__ void k_qg(const int* __restrict__ nidx, const int* __restrict__ nmask,
                     const float* __restrict__ qg, const float* __restrict__ qb,
                     const float* __restrict__ bch) {
    __shared__ float wc[2048];
    __shared__ float bs[128];
    int t = threadIdx.x;
    for (int e = t; e < 2048; e += 256) wc[e] = g_Wc2[e];
    for (int e = t; e < 128; e += 256) bs[e] = bch[e];
    __syncthreads();
    int lane = t & 31, w = t >> 5;
    int i = blockIdx.x * 8 + w;
    if (i >= NPTS) return;
    int v = lane & 15, h = lane >> 4;

    float qp = 0.f;
#pragma unroll
    for (int tt = 0; tt < 14; ++tt) {
        int k = 2 * tt + h;
        bool ok = (k < KOFF);
        int m = ok ? nmask[(size_t)k * NPTS + i] : 0;
        int j = ok ? nidx[(size_t)k * NPTS + i] : 0;
        float val = m ? g_Y[(size_t)j * NQ + k * 16 + v] : 0.f;
        qp += val;
    }
    qp += __shfl_xor_sync(0xffffffffu, qp, 16);
    float qf = fmaxf(qp * qg[v] + qb[v], 0.f);
    float qa[16];
#pragma unroll
    for (int vv = 0; vv < 16; ++vv) qa[vv] = __shfl_sync(0xffffffffu, qf, vv);

    float4 av = ((const float4*)bs)[lane];
#pragma unroll
    for (int vv = 0; vv < 16; ++vv) {
        float4 wv4 = *(const float4*)(wc + vv * 128 + lane * 4);
        av.x += qa[vv] * wv4.x; av.y += qa[vv] * wv4.y;
        av.z += qa[vv] * wv4.z; av.w += qa[vv] * wv4.w;
    }
    float s = fmaxf(av.x, 0.f) + fmaxf(av.y, 0.f) + fmaxf(av.z, 0.f) + fmaxf(av.w, 0.f);
#pragma unroll
    for (int d = 16; d; d >>= 1) s += __shfl_xor_sync(0xffffffffu, s, d);
    if (lane == 0) g_choice[i] = s;
}

// ================= attention (rank-1 scores) + weighted aggregation ==========
__global__ void k_attn(const int* __restrict__ nidx, const int* __restrict__ nmask) {
    int lane = threadIdx.x & 31;
    int wid = threadIdx.x >> 5;
    int i = blockIdx.x * 8 + wid;
    if (i >= NPTS) return;
    float tC = g_C[0] * g_choice[i];
    int m = 0, j = 0;
    float s = -1e9f;
    if (lane < KOFF) {
        m = nmask[(size_t)lane * NPTS + i];
        j = nidx[(size_t)lane * NPTS + i];
        s = m ? tC * g_choice[j] : -1e9f;
    }
    float mx = s;
#pragma unroll
    for (int d = 16; d; d >>= 1) mx = fmaxf(mx, __shfl_xor_sync(0xffffffffu, mx, d));
    float e = (lane < KOFF && m) ? expf(s - mx) : 0.f;
    float se = e;
#pragma unroll
    for (int d = 16; d; d >>= 1) se += __shfl_xor_sync(0xffffffffu, se, d);
    float a = e / se;

    float4 acc = {0.f, 0.f, 0.f, 0.f};
    for (int k = 0; k < KOFF; ++k) {
        float ak = __shfl_sync(0xffffffffu, a, k);
        int jk = __shfl_sync(0xffffffffu, j, k);
        int mk = __shfl_sync(0xffffffffu, m, k);
        if (mk) {
            float4 v = ((const float4*)g_vf)[(size_t)jk * 32 + lane];
            acc.x += ak * v.x; acc.y += ak * v.y; acc.z += ak * v.z; acc.w += ak * v.w;
        }
    }
    ((float4*)g_agg)[(size_t)i * 32 + lane] = acc;
}

// ================= launch ====================================================
extern "C" void kernel_launch(void* const* d_in, const int* in_sizes, int n_in,
                              void* d_out, int out_size) {
    const float* x      = (const float*)d_in[0];
    const float* coords = (const float*)d_in[1];
    const float* Wq     = (const float*)d_in[2];
    const float* qg     = (const float*)d_in[3];
    const float* qb     = (const float*)d_in[4];
    const float* Wv     = (const float*)d_in[5];
    const float* vg     = (const float*)d_in[6];
    const float* vb     = (const float*)d_in[7];
    const float* cb     = (const float*)d_in[8];
    const float* Wch    = (const float*)d_in[9];
    const float* bch    = (const float*)d_in[10];
    const float* Wpos   = (const float*)d_in[11];
    const float* bpos   = (const float*)d_in[12];
    const float* Wo     = (const float*)d_in[13];
    const float* ogm    = (const float*)d_in[14];
    const float* obt    = (const float*)d_in[15];
    const int*   nidx   = (const int*)d_in[16];
    const int*   nmask  = (const int*)d_in[17];
    float* out = (float*)d_out;

    size_t smYV = (size_t)(128 * XPITCH + 128 * 144) * 4;  // 141312
    size_t smO  = (size_t)(128 * XPITCH + 128 * 128) * 4;  // 133120
    cudaFuncSetAttribute(k_gemmYV, cudaFuncAttributeMaxDynamicSharedMemorySize, (int)smYV);
    cudaFuncSetAttribute(k_gemmO,  cudaFuncAttributeMaxDynamicSharedMemorySize, (int)smO);

    int mblocks = (NPTS + 127) / 128;  // 782

    k_prep<<<KOFF + 1, 256>>>(cb, Wch, Wq);
    k_gemmYV<<<mblocks, 288, smYV>>>(x, Wv, vg, vb, coords, Wpos, bpos);
    k_qg<<<(NPTS + 7) / 8, 256>>>(nidx, nmask, qg, qb, bch);
    k_attn<<<(NPTS + 7) / 8, 256>>>(nidx, nmask);
    k_gemmO<<<mblocks, 256, smO>>>(Wo, ogm, obt, x, out);
}

// round 8
// speedup vs baseline: 2.5336x; 1.3051x over previous
#include <cuda_runtime.h>
#include <cuda_bf16.h>
#include <cstdint>

#define NPTS 100000
#define KOFF 27
#define PL 128
#define VD 16
#define NQ 432      // 27*16
#define NTOT 560    // 432 Y cols + 128 vf cols
#define XPITCH 132  // floats; FFMA2 out-GEMM
#define KP 136      // bf16 pitch for mma smem tiles (272 bytes/row)

// ---- scratch (device globals; no allocation) ----
__device__ __align__(16) float g_Y[(size_t)NPTS * NQ];
__device__ __align__(16) float g_vf[(size_t)NPTS * PL];
__device__ __align__(16) float g_agg[(size_t)NPTS * PL];
__device__ float g_choice[NPTS];
__device__ __align__(16) float g_Wc2[VD * PL];
__device__ float g_C[1];
// dense bf16 hi/lo W images: [NTOT][128]
__device__ __align__(16) __nv_bfloat16 g_Wih[(size_t)NTOT * 128];
__device__ __align__(16) __nv_bfloat16 g_Wil[(size_t)NTOT * 128];

// ---- packed f32x2 helpers (FFMA2 path, out-GEMM) ----
__device__ __forceinline__ unsigned long long pk2(float lo, float hi) {
    unsigned long long r;
    asm("mov.b64 %0, {%1,%2};" : "=l"(r) : "f"(lo), "f"(hi));
    return r;
}
__device__ __forceinline__ void fma2(unsigned long long& c, unsigned long long a,
                                     unsigned long long b) {
    asm("fma.rn.f32x2 %0, %1, %2, %0;" : "+l"(c) : "l"(a), "l"(b));
}
__device__ __forceinline__ float2 upk2(unsigned long long v) {
    float2 r;
    asm("mov.b64 {%0,%1}, %2;" : "=f"(r.x), "=f"(r.y) : "l"(v));
    return r;
}

// ---- warp mma.sync m16n8k16 bf16 (sm_80+ PTX; legal under compute_103) ----
__device__ __forceinline__ void mma16816(float* c, const uint32_t* a,
                                         uint32_t b0, uint32_t b1) {
    asm volatile(
        "mma.sync.aligned.m16n8k16.row.col.f32.bf16.bf16.f32 "
        "{%0,%1,%2,%3}, {%4,%5,%6,%7}, {%8,%9}, {%0,%1,%2,%3};"
        : "+f"(c[0]), "+f"(c[1]), "+f"(c[2]), "+f"(c[3])
        : "r"(a[0]), "r"(a[1]), "r"(a[2]), "r"(a[3]), "r"(b0), "r"(b1));
}

// ================= prep =====================================================
// blocks 0..13: dense bf16 hi/lo W images (40 rows each). block 14: Wc2 + C.
__global__ void k_prep(const float* __restrict__ cb, const float* __restrict__ Wch,
                       const float* __restrict__ Wq, const float* __restrict__ Wv) {
    int b = blockIdx.x, t = threadIdx.x;
    if (b < 14) {
        for (int e = t; e < 5120; e += 256) {
            int idx = b * 5120 + e;
            int n = idx >> 7, k = idx & 127;
            float v = (n < NQ) ? Wq[(size_t)(n >> 4) * 2048 + k * 16 + (n & 15)]
                               : Wv[(size_t)k * 128 + (n - NQ)];
            __nv_bfloat16 hi = __float2bfloat16(v);
            __nv_bfloat16 lo = __float2bfloat16(v - __bfloat162float(hi));
            g_Wih[(size_t)n * 128 + k] = hi;
            g_Wil[(size_t)n * 128 + k] = lo;
        }
    } else {
        for (int e = t; e < VD * PL; e += 256) {
            int v = e >> 7, o = e & 127;
            float s = 0.f;
#pragma unroll
            for (int r = 0; r < 8; ++r) s += cb[8 * v + r] * Wch[(8 * v + r) * PL + o];
            g_Wc2[e] = s;
        }
        if (t == 0) {
            float c = 0.f;
            for (int i = 0; i < PL; ++i) c += cb[i] * cb[i];
            g_C[0] = c;
        }
    }
}

// ================= split-bf16 mma.sync Y + vf GEMM ==========================
// 256 threads = 8 warps; 128 points/block; N processed in 5 chunks of 112.
// A hi/lo K-major pitch-KP in smem; A fragments cached in registers.
__global__ __launch_bounds__(256) void k_mmaYV(
        const float* __restrict__ x, const float* __restrict__ vg,
        const float* __restrict__ vb, const float* __restrict__ coords,
        const float* __restrict__ Wpos, const float* __restrict__ bpos) {
    extern __shared__ __align__(16) char smem[];
    __nv_bfloat16* Ah = (__nv_bfloat16*)smem;        // 128*KP
    __nv_bfloat16* Al = Ah + 128 * KP;
    __nv_bfloat16* Wh = Al + 128 * KP;               // 112*KP
    __nv_bfloat16* Wl = Wh + 112 * KP;
    float* pos_s = (float*)(Wl + 112 * KP);          // [128][16]
    int t = threadIdx.x, lane = t & 31, w = t >> 5;
    int i0 = blockIdx.x * 128;

    // ---- A build: x -> bf16 hi/lo, K-major ----
    for (int e = t; e < 2048; e += 256) {
        int m = e >> 4, kb = e & 15;
        int gi = i0 + m;
        float xs[8];
        if (gi < NPTS) {
            float4 a = ((const float4*)x)[(size_t)gi * 32 + kb * 2];
            float4 b = ((const float4*)x)[(size_t)gi * 32 + kb * 2 + 1];
            xs[0] = a.x; xs[1] = a.y; xs[2] = a.z; xs[3] = a.w;
            xs[4] = b.x; xs[5] = b.y; xs[6] = b.z; xs[7] = b.w;
        } else {
#pragma unroll
            for (int j = 0; j < 8; ++j) xs[j] = 0.f;
        }
        union { __nv_bfloat16 h[8]; uint4 v; } uh, ul;
#pragma unroll
        for (int j = 0; j < 8; ++j) {
            __nv_bfloat16 hi = __float2bfloat16(xs[j]);
            uh.h[j] = hi;
            ul.h[j] = __float2bfloat16(xs[j] - __bfloat162float(hi));
        }
        *(uint4*)((char*)Ah + m * (KP * 2) + kb * 16) = uh.v;
        *(uint4*)((char*)Al + m * (KP * 2) + kb * 16) = ul.v;
    }
    // ---- pos table ----
    for (int e = t; e < 2048; e += 256) {
        int m = e >> 4, ng = e & 15;
        int gi = i0 + m;
        float p = 0.f;
        if (gi < NPTS) {
            float cx = coords[(size_t)gi * 3], cy = coords[(size_t)gi * 3 + 1],
                  cz = coords[(size_t)gi * 3 + 2];
            p = cx * Wpos[ng] + cy * Wpos[16 + ng] + cz * Wpos[32 + ng] + bpos[ng];
        }
        pos_s[e] = p;
    }
    __syncthreads();

    // ---- cache A fragments for all 8 k-steps ----
    int gr = lane >> 2, cq = (lane & 3) * 2;
    const char* Ar0h = (const char*)Ah + (w * 16 + gr) * (KP * 2);
    const char* Ar0l = (const char*)Al + (w * 16 + gr) * (KP * 2);
    uint32_t ahf[8][4], alf[8][4];
#pragma unroll
    for (int k = 0; k < 8; ++k) {
        int k0 = k * 16;
        ahf[k][0] = *(const uint32_t*)(Ar0h + (k0 + cq) * 2);
        ahf[k][1] = *(const uint32_t*)(Ar0h + 8 * (KP * 2) + (k0 + cq) * 2);
        ahf[k][2] = *(const uint32_t*)(Ar0h + (k0 + cq + 8) * 2);
        ahf[k][3] = *(const uint32_t*)(Ar0h + 8 * (KP * 2) + (k0 + cq + 8) * 2);
        alf[k][0] = *(const uint32_t*)(Ar0l + (k0 + cq) * 2);
        alf[k][1] = *(const uint32_t*)(Ar0l + 8 * (KP * 2) + (k0 + cq) * 2);
        alf[k][2] = *(const uint32_t*)(Ar0l + (k0 + cq + 8) * 2);
        alf[k][3] = *(const uint32_t*)(Ar0l + 8 * (KP * 2) + (k0 + cq + 8) * 2);
    }

    int gi0 = i0 + w * 16 + gr, gi1 = gi0 + 8;

    for (int c = 0; c < 5; ++c) {
        __syncthreads();  // previous chunk's reads of W smem done
        for (int e = t; e < 112 * 16; e += 256) {
            int row = e >> 4, q = e & 15;
            size_t gsrc = ((size_t)(c * 112 + row) * 256 + q * 16) >> 4;
            *(uint4*)((char*)Wh + row * (KP * 2) + q * 16) = ((const uint4*)g_Wih)[gsrc];
            *(uint4*)((char*)Wl + row * (KP * 2) + q * 16) = ((const uint4*)g_Wil)[gsrc];
        }
        __syncthreads();

#pragma unroll 2
        for (int nt = 0; nt < 14; ++nt) {
            int nc = c * 112 + nt * 8;
            const char* Bh = (const char*)Wh + (nt * 8 + gr) * (KP * 2) + cq * 2;
            const char* Bl = (const char*)Wl + (nt * 8 + gr) * (KP * 2) + cq * 2;
            float acc[4] = {0.f, 0.f, 0.f, 0.f};
#pragma unroll
            for (int k = 0; k < 8; ++k) {
                int kb = k * 32;  // k0*2 bytes
                uint32_t bh0 = *(const uint32_t*)(Bh + kb);
                uint32_t bh1 = *(const uint32_t*)(Bh + kb + 16);
                uint32_t bl0 = *(const uint32_t*)(Bl + kb);
                uint32_t bl1 = *(const uint32_t*)(Bl + kb + 16);
                mma16816(acc, ahf[k], bh0, bh1);
                mma16816(acc, alf[k], bh0, bh1);
                mma16816(acc, ahf[k], bl0, bl1);
            }
            if (nc < NQ) {
                if (gi0 < NPTS)
                    *(float2*)(g_Y + (size_t)gi0 * NQ + nc + cq) = make_float2(acc[0], acc[1]);
                if (gi1 < NPTS)
                    *(float2*)(g_Y + (size_t)gi1 * NQ + nc + cq) = make_float2(acc[2], acc[3]);
            } else {
                int v = nc - NQ + cq;
                float g0 = vg[v], g1 = vg[v + 1], b0 = vb[v], b1 = vb[v + 1];
                if (gi0 < NPTS) {
                    float p = pos_s[(w * 16 + gr) * 16 + (v >> 3)];
                    *(float2*)(g_vf + (size_t)gi0 * PL + v) = make_float2(
                        fmaxf(acc[0] * g0 + b0, 0.f) + p, fmaxf(acc[1] * g1 + b1, 0.f) + p);
                }
                if (gi1 < NPTS) {
                    float p = pos_s[(w * 16 + gr + 8) * 16 + (v >> 3)];
                    *(float2*)(g_vf + (size_t)gi1 * PL + v) = make_float2(
                        fmaxf(acc[2] * g0 + b0, 0.f) + p, fmaxf(acc[3] * g1 + b1, 0.f) + p);
                }
            }
        }
    }
}

// ================= out GEMM: relu((agg@Wo)*g+b) + x (FFMA2) =================
__global__ void k_gemmO(const float* __restrict__ Wo, const float* __restrict__ g1,
                        const float* __restrict__ b1, const float* __restrict__ resid,
                        float* __restrict__ Out) {
    constexpr int BN = 128;
    constexpr int T = 256;
    extern __shared__ float sm[];
    float* xg = sm;
    float* wg = sm + 128 * XPITCH;
    int t = threadIdx.x;
    int i0 = blockIdx.x * 128;
    int mg = t & 15, ng = t >> 4;

    for (int e = t; e < 4096; e += T) {
        int ml = e & 7, c4 = (e >> 3) & 31, mb = e >> 8;
        int m = mb * 8 + ml;
        int gi = i0 + m;
        float4 v = (gi < NPTS) ? ((const float4*)g_agg)[(size_t)gi * 32 + c4]
                               : make_float4(0.f, 0.f, 0.f, 0.f);
        int cc = c4 * 4;
        xg[(cc + 0) * XPITCH + m] = v.x; xg[(cc + 1) * XPITCH + m] = v.y;
        xg[(cc + 2) * XPITCH + m] = v.z; xg[(cc + 3) * XPITCH + m] = v.w;
    }
    for (int e = t; e < 128 * 32; e += T)
        ((float4*)wg)[e] = ((const float4*)Wo)[e];
    __syncthreads();

    unsigned long long acc[32];
#pragma unroll
    for (int q = 0; q < 32; ++q) acc[q] = 0ull;

#pragma unroll 4
    for (int c = 0; c < 128; ++c) {
        const float4* xp = (const float4*)(xg + c * XPITCH + mg * 8);
        float4 xa = xp[0], xb = xp[1];
        const float4* wp = (const float4*)(wg + c * BN + ng * 8);
        float4 wa = wp[0], wb = wp[1];
        unsigned long long xk0 = pk2(xa.x, xa.y), xk1 = pk2(xa.z, xa.w);
        unsigned long long xk2 = pk2(xb.x, xb.y), xk3 = pk2(xb.z, xb.w);
        float wv[8] = {wa.x, wa.y, wa.z, wa.w, wb.x, wb.y, wb.z, wb.w};
#pragma unroll
        for (int j = 0; j < 8; ++j) {
            unsigned long long wd = pk2(wv[j], wv[j]);
            fma2(acc[0 * 8 + j], xk0, wd);
            fma2(acc[1 * 8 + j], xk1, wd);
            fma2(acc[2 * 8 + j], xk2, wd);
            fma2(acc[3 * 8 + j], xk3, wd);
        }
    }

    float ga[8], bb[8];
#pragma unroll
    for (int j = 0; j < 8; ++j) { ga[j] = g1[ng * 8 + j]; bb[j] = b1[ng * 8 + j]; }
#pragma unroll
    for (int i2 = 0; i2 < 4; ++i2) {
#pragma unroll
        for (int p = 0; p < 2; ++p) {
            int gi = i0 + mg * 8 + i2 * 2 + p;
            if (gi >= NPTS) continue;
            const float4* r4 = (const float4*)(resid + (size_t)gi * 128 + ng * 8);
            float4 ra = r4[0], rb = r4[1];
            float rr[8] = {ra.x, ra.y, ra.z, ra.w, rb.x, rb.y, rb.z, rb.w};
            float v[8];
#pragma unroll
            for (int j = 0; j < 8; ++j) {
                float2 u = upk2(acc[i2 * 8 + j]);
                v[j] = fmaxf((p ? u.y : u.x) * ga[j] + bb[j], 0.f) + rr[j];
            }
            float4* o4 = (float4*)(Out + (size_t)gi * 128 + ng * 8);
            o4[0] = make_float4(v[0], v[1], v[2], v[3]);
            o4[1] = make_float4(v[4], v[5], v[6], v[7]);
        }
    }
}

// ================= masked gather of Y + BN/relu + choice ====================
__global__ void k_qg(const int* __restrict__ nidx, const int* __restrict__ nmask,
                     const float* __restrict__ qg, const float* __restrict__ qb,
                     const float* __restrict__ bch) {
    __shared__ float wc[2048];
    __shared__ float bs[128];
    int t = threadIdx.x;
    for (int e = t; e < 2048; e += 256) wc[e] = g_Wc2[e];
    for (int e = t; e < 128; e += 256) bs[e] = bch[e];
    __syncthreads();
    int lane = t & 31, w = t >> 5;
    int i = blockIdx.x * 8 + w;
    if (i >= NPTS) return;
    int v = lane & 15, h = lane >> 4;

    float qp = 0.f;
#pragma unroll
    for (int tt = 0; tt < 14; ++tt) {
        int k = 2 * tt + h;
        bool ok = (k < KOFF);
        int m = ok ? nmask[(size_t)k * NPTS + i] : 0;
        int j = ok ? nidx[(size_t)k * NPTS + i] : 0;
        float val = m ? g_Y[(size_t)j * NQ + k * 16 + v] : 0.f;
        qp += val;
    }
    qp += __shfl_xor_sync(0xffffffffu, qp, 16);
    float qf = fmaxf(qp * qg[v] + qb[v], 0.f);
    float qa[16];
#pragma unroll
    for (int vv = 0; vv < 16; ++vv) qa[vv] = __shfl_sync(0xffffffffu, qf, vv);

    float4 av = ((const float4*)bs)[lane];
#pragma unroll
    for (int vv = 0; vv < 16; ++vv) {
        float4 wv4 = *(const float4*)(wc + vv * 128 + lane * 4);
        av.x += qa[vv] * wv4.x; av.y += qa[vv] * wv4.y;
        av.z += qa[vv] * wv4.z; av.w += qa[vv] * wv4.w;
    }
    float s = fmaxf(av.x, 0.f) + fmaxf(av.y, 0.f) + fmaxf(av.z, 0.f) + fmaxf(av.w, 0.f);
#pragma unroll
    for (int d = 16; d; d >>= 1) s += __shfl_xor_sync(0xffffffffu, s, d);
    if (lane == 0) g_choice[i] = s;
}

// ================= attention (rank-1 scores) + weighted aggregation ==========
__global__ void k_attn(const int* __restrict__ nidx, const int* __restrict__ nmask) {
    int lane = threadIdx.x & 31;
    int wid = threadIdx.x >> 5;
    int i = blockIdx.x * 8 + wid;
    if (i >= NPTS) return;
    float tC = g_C[0] * g_choice[i];
    int m = 0, j = 0;
    float s = -1e9f;
    if (lane < KOFF) {
        m = nmask[(size_t)lane * NPTS + i];
        j = nidx[(size_t)lane * NPTS + i];
        s = m ? tC * g_choice[j] : -1e9f;
    }
    float mx = s;
#pragma unroll
    for (int d = 16; d; d >>= 1) mx = fmaxf(mx, __shfl_xor_sync(0xffffffffu, mx, d));
    float e = (lane < KOFF && m) ? expf(s - mx) : 0.f;
    float se = e;
#pragma unroll
    for (int d = 16; d; d >>= 1) se += __shfl_xor_sync(0xffffffffu, se, d);
    float a = e / se;

    float4 acc = {0.f, 0.f, 0.f, 0.f};
    for (int k = 0; k < KOFF; ++k) {
        float ak = __shfl_sync(0xffffffffu, a, k);
        int jk = __shfl_sync(0xffffffffu, j, k);
        int mk = __shfl_sync(0xffffffffu, m, k);
        if (mk) {
            float4 v = ((const float4*)g_vf)[(size_t)jk * 32 + lane];
            acc.x += ak * v.x; acc.y += ak * v.y; acc.z += ak * v.z; acc.w += ak * v.w;
        }
    }
    ((float4*)g_agg)[(size_t)i * 32 + lane] = acc;
}

// ================= launch ====================================================
extern "C" void kernel_launch(void* const* d_in, const int* in_sizes, int n_in,
                              void* d_out, int out_size) {
    const float* x      = (const float*)d_in[0];
    const float* coords = (const float*)d_in[1];
    const float* Wq     = (const float*)d_in[2];
    const float* qg     = (const float*)d_in[3];
    const float* qb     = (const float*)d_in[4];
    const float* Wv     = (const float*)d_in[5];
    const float* vg     = (const float*)d_in[6];
    const float* vb     = (const float*)d_in[7];
    const float* cb     = (const float*)d_in[8];
    const float* Wch    = (const float*)d_in[9];
    const float* bch    = (const float*)d_in[10];
    const float* Wpos   = (const float*)d_in[11];
    const float* bpos   = (const float*)d_in[12];
    const float* Wo     = (const float*)d_in[13];
    const float* ogm    = (const float*)d_in[14];
    const float* obt    = (const float*)d_in[15];
    const int*   nidx   = (const int*)d_in[16];
    const int*   nmask  = (const int*)d_in[17];
    float* out = (float*)d_out;

    // smem: A hi/lo 2*128*KP*2 + W hi/lo 2*112*KP*2 + pos 128*16*4
    size_t smMMA = (size_t)(2 * 128 * KP * 2) + (size_t)(2 * 112 * KP * 2) + 128 * 16 * 4;
    size_t smO   = (size_t)(128 * XPITCH + 128 * 128) * 4;
    cudaFuncSetAttribute(k_mmaYV, cudaFuncAttributeMaxDynamicSharedMemorySize, (int)smMMA);
    cudaFuncSetAttribute(k_gemmO, cudaFuncAttributeMaxDynamicSharedMemorySize, (int)smO);

    int mblocks = (NPTS + 127) / 128;  // 782

    k_prep<<<15, 256>>>(cb, Wch, Wq, Wv);
    k_mmaYV<<<mblocks, 256, smMMA>>>(x, vg, vb, coords, Wpos, bpos);
    k_qg<<<(NPTS + 7) / 8, 256>>>(nidx, nmask, qg, qb, bch);
    k_attn<<<(NPTS + 7) / 8, 256>>>(nidx, nmask);
    k_gemmO<<<mblocks, 256, smO>>>(Wo, ogm, obt, x, out);
}

// round 9
// speedup vs baseline: 3.0457x; 1.2021x over previous
#include <cuda_runtime.h>
#include <cuda_bf16.h>
#include <cstdint>

#define NPTS 100000
#define KOFF 27
#define PL 128
#define VD 16
#define NQ 432      // 27*16
#define NTOT 688    // 432 Y + 128 vf + 128 out cols
#define KP 136      // bf16 pitch for mma smem tiles (272 bytes/row)

// ---- scratch (device globals; no allocation) ----
__device__ __align__(16) float g_Y[(size_t)NPTS * NQ];
__device__ __align__(16) float g_vf[(size_t)NPTS * PL];
__device__ __align__(16) float g_agg[(size_t)NPTS * PL];
__device__ float g_choice[NPTS];
__device__ __align__(16) float g_Wc2[VD * PL];
__device__ float g_C[1];
// dense bf16 hi/lo W images: [NTOT][128]
__device__ __align__(16) __nv_bfloat16 g_Wih[(size_t)NTOT * 128];
__device__ __align__(16) __nv_bfloat16 g_Wil[(size_t)NTOT * 128];

// ---- warp mma.sync m16n8k16 bf16 ----
__device__ __forceinline__ void mma16816(float* c, const uint32_t* a,
                                         uint32_t b0, uint32_t b1) {
    asm volatile(
        "mma.sync.aligned.m16n8k16.row.col.f32.bf16.bf16.f32 "
        "{%0,%1,%2,%3}, {%4,%5,%6,%7}, {%8,%9}, {%0,%1,%2,%3};"
        : "+f"(c[0]), "+f"(c[1]), "+f"(c[2]), "+f"(c[3])
        : "r"(a[0]), "r"(a[1]), "r"(a[2]), "r"(a[3]), "r"(b0), "r"(b1));
}

// ================= prep =====================================================
// blocks 0..17: dense bf16 hi/lo W images. block 18: Wc2 + C.
__global__ void k_prep(const float* __restrict__ cb, const float* __restrict__ Wch,
                       const float* __restrict__ Wq, const float* __restrict__ Wv,
                       const float* __restrict__ Wo) {
    int b = blockIdx.x, t = threadIdx.x;
    if (b < 18) {
        for (int e = t; e < 5120; e += 256) {
            int idx = b * 5120 + e;
            if (idx >= NTOT * 128) break;
            int n = idx >> 7, k = idx & 127;
            float v;
            if (n < NQ)            v = Wq[(size_t)(n >> 4) * 2048 + k * 16 + (n & 15)];
            else if (n < NQ + 128) v = Wv[(size_t)k * 128 + (n - NQ)];
            else                   v = Wo[(size_t)k * 128 + (n - NQ - 128)];
            __nv_bfloat16 hi = __float2bfloat16(v);
            __nv_bfloat16 lo = __float2bfloat16(v - __bfloat162float(hi));
            g_Wih[(size_t)n * 128 + k] = hi;
            g_Wil[(size_t)n * 128 + k] = lo;
        }
    } else {
        for (int e = t; e < VD * PL; e += 256) {
            int v = e >> 7, o = e & 127;
            float s = 0.f;
#pragma unroll
            for (int r = 0; r < 8; ++r) s += cb[8 * v + r] * Wch[(8 * v + r) * PL + o];
            g_Wc2[e] = s;
        }
        if (t == 0) {
            float c = 0.f;
            for (int i = 0; i < PL; ++i) c += cb[i] * cb[i];
            g_C[0] = c;
        }
    }
}

// ---- shared device helpers for the mma kernels ----
// Build bf16 hi/lo A tile (K-major pitch KP) from fp32 src [N x 128]
__device__ __forceinline__ void build_A(const float* __restrict__ src, int i0,
                                        __nv_bfloat16* Ah, __nv_bfloat16* Al, int t) {
    for (int e = t; e < 2048; e += 256) {
        int m = e >> 4, kb = e & 15;
        int gi = i0 + m;
        float xs[8];
        if (gi < NPTS) {
            float4 a = ((const float4*)src)[(size_t)gi * 32 + kb * 2];
            float4 b = ((const float4*)src)[(size_t)gi * 32 + kb * 2 + 1];
            xs[0] = a.x; xs[1] = a.y; xs[2] = a.z; xs[3] = a.w;
            xs[4] = b.x; xs[5] = b.y; xs[6] = b.z; xs[7] = b.w;
        } else {
#pragma unroll
            for (int j = 0; j < 8; ++j) xs[j] = 0.f;
        }
        union { __nv_bfloat16 h[8]; uint4 v; } uh, ul;
#pragma unroll
        for (int j = 0; j < 8; ++j) {
            __nv_bfloat16 hi = __float2bfloat16(xs[j]);
            uh.h[j] = hi;
            ul.h[j] = __float2bfloat16(xs[j] - __bfloat162float(hi));
        }
        *(uint4*)((char*)Ah + m * (KP * 2) + kb * 16) = uh.v;
        *(uint4*)((char*)Al + m * (KP * 2) + kb * 16) = ul.v;
    }
}
// Cache A fragments (8 k-steps) for this thread's 16-row slab
__device__ __forceinline__ void load_Afrag(const __nv_bfloat16* A, int row0,
                                           int gr, int cq, uint32_t f[8][4]) {
    const char* r0 = (const char*)A + (row0 + gr) * (KP * 2);
#pragma unroll
    for (int k = 0; k < 8; ++k) {
        int k0 = k * 16;
        f[k][0] = *(const uint32_t*)(r0 + (k0 + cq) * 2);
        f[k][1] = *(const uint32_t*)(r0 + 8 * (KP * 2) + (k0 + cq) * 2);
        f[k][2] = *(const uint32_t*)(r0 + (k0 + cq + 8) * 2);
        f[k][3] = *(const uint32_t*)(r0 + 8 * (KP * 2) + (k0 + cq + 8) * 2);
    }
}

// ================= split-bf16 mma.sync Y + vf GEMM ==========================
__global__ __launch_bounds__(256) void k_mmaYV(
        const float* __restrict__ x, const float* __restrict__ vg,
        const float* __restrict__ vb, const float* __restrict__ coords,
        const float* __restrict__ Wpos, const float* __restrict__ bpos) {
    extern __shared__ __align__(16) char smem[];
    __nv_bfloat16* Ah = (__nv_bfloat16*)smem;        // 128*KP
    __nv_bfloat16* Al = Ah + 128 * KP;
    __nv_bfloat16* Wh = Al + 128 * KP;               // 112*KP
    __nv_bfloat16* Wl = Wh + 112 * KP;
    float* pos_s = (float*)(Wl + 112 * KP);          // [128][16]
    int t = threadIdx.x, lane = t & 31, w = t >> 5;
    int i0 = blockIdx.x * 128;

    build_A(x, i0, Ah, Al, t);
    for (int e = t; e < 2048; e += 256) {
        int m = e >> 4, ng = e & 15;
        int gi = i0 + m;
        float p = 0.f;
        if (gi < NPTS) {
            float cx = coords[(size_t)gi * 3], cy = coords[(size_t)gi * 3 + 1],
                  cz = coords[(size_t)gi * 3 + 2];
            p = cx * Wpos[ng] + cy * Wpos[16 + ng] + cz * Wpos[32 + ng] + bpos[ng];
        }
        pos_s[e] = p;
    }
    __syncthreads();

    int gr = lane >> 2, cq = (lane & 3) * 2;
    uint32_t ahf[8][4], alf[8][4];
    load_Afrag(Ah, w * 16, gr, cq, ahf);
    load_Afrag(Al, w * 16, gr, cq, alf);

    int gi0 = i0 + w * 16 + gr, gi1 = gi0 + 8;

    for (int c = 0; c < 5; ++c) {
        __syncthreads();
        for (int e = t; e < 112 * 16; e += 256) {
            int row = e >> 4, q = e & 15;
            size_t gsrc = ((size_t)(c * 112 + row) * 256 + q * 16) >> 4;
            *(uint4*)((char*)Wh + row * (KP * 2) + q * 16) = ((const uint4*)g_Wih)[gsrc];
            *(uint4*)((char*)Wl + row * (KP * 2) + q * 16) = ((const uint4*)g_Wil)[gsrc];
        }
        __syncthreads();

#pragma unroll 2
        for (int nt = 0; nt < 14; ++nt) {
            int nc = c * 112 + nt * 8;
            const char* Bh = (const char*)Wh + (nt * 8 + gr) * (KP * 2) + cq * 2;
            const char* Bl = (const char*)Wl + (nt * 8 + gr) * (KP * 2) + cq * 2;
            float a1[4] = {0.f, 0.f, 0.f, 0.f};   // hi*hi
            float a2[4] = {0.f, 0.f, 0.f, 0.f};   // lo*hi
            float a3[4] = {0.f, 0.f, 0.f, 0.f};   // hi*lo
#pragma unroll
            for (int k = 0; k < 8; ++k) {
                int kb = k * 32;
                uint32_t bh0 = *(const uint32_t*)(Bh + kb);
                uint32_t bh1 = *(const uint32_t*)(Bh + kb + 16);
                uint32_t bl0 = *(const uint32_t*)(Bl + kb);
                uint32_t bl1 = *(const uint32_t*)(Bl + kb + 16);
                mma16816(a1, ahf[k], bh0, bh1);
                mma16816(a2, alf[k], bh0, bh1);
                mma16816(a3, ahf[k], bl0, bl1);
            }
            float acc[4];
#pragma unroll
            for (int q = 0; q < 4; ++q) acc[q] = a1[q] + (a2[q] + a3[q]);
            if (nc < NQ) {
                if (gi0 < NPTS)
                    *(float2*)(g_Y + (size_t)gi0 * NQ + nc + cq) = make_float2(acc[0], acc[1]);
                if (gi1 < NPTS)
                    *(float2*)(g_Y + (size_t)gi1 * NQ + nc + cq) = make_float2(acc[2], acc[3]);
            } else {
                int v = nc - NQ + cq;
                float g0 = vg[v], g1 = vg[v + 1], b0 = vb[v], b1 = vb[v + 1];
                if (gi0 < NPTS) {
                    float p = pos_s[(w * 16 + gr) * 16 + (v >> 3)];
                    *(float2*)(g_vf + (size_t)gi0 * PL + v) = make_float2(
                        fmaxf(acc[0] * g0 + b0, 0.f) + p, fmaxf(acc[1] * g1 + b1, 0.f) + p);
                }
                if (gi1 < NPTS) {
                    float p = pos_s[(w * 16 + gr + 8) * 16 + (v >> 3)];
                    *(float2*)(g_vf + (size_t)gi1 * PL + v) = make_float2(
                        fmaxf(acc[2] * g0 + b0, 0.f) + p, fmaxf(acc[3] * g1 + b1, 0.f) + p);
                }
            }
        }
    }
}

// ================= split-bf16 mma.sync out GEMM =============================
// out = relu((agg@Wo)*g+b) + x ; W_out rows 560..687 of the prepped image.
__global__ __launch_bounds__(256) void k_mmaO(
        const float* __restrict__ ogm, const float* __restrict__ obt,
        const float* __restrict__ resid, float* __restrict__ Out) {
    extern __shared__ __align__(16) char smem[];
    __nv_bfloat16* Ah = (__nv_bfloat16*)smem;
    __nv_bfloat16* Al = Ah + 128 * KP;
    __nv_bfloat16* Wh = Al + 128 * KP;               // 128*KP
    __nv_bfloat16* Wl = Wh + 128 * KP;
    int t = threadIdx.x, lane = t & 31, w = t >> 5;
    int i0 = blockIdx.x * 128;

    build_A(g_agg, i0, Ah, Al, t);
    for (int e = t; e < 128 * 16; e += 256) {
        int row = e >> 4, q = e & 15;
        size_t gsrc = ((size_t)(560 + row) * 256 + q * 16) >> 4;
        *(uint4*)((char*)Wh + row * (KP * 2) + q * 16) = ((const uint4*)g_Wih)[gsrc];
        *(uint4*)((char*)Wl + row * (KP * 2) + q * 16) = ((const uint4*)g_Wil)[gsrc];
    }
    __syncthreads();

    int gr = lane >> 2, cq = (lane & 3) * 2;
    uint32_t ahf[8][4], alf[8][4];
    load_Afrag(Ah, w * 16, gr, cq, ahf);
    load_Afrag(Al, w * 16, gr, cq, alf);

    int gi0 = i0 + w * 16 + gr, gi1 = gi0 + 8;

#pragma unroll 2
    for (int nt = 0; nt < 16; ++nt) {
        int nc = nt * 8;
        const char* Bh = (const char*)Wh + (nt * 8 + gr) * (KP * 2) + cq * 2;
        const char* Bl = (const char*)Wl + (nt * 8 + gr) * (KP * 2) + cq * 2;
        float a1[4] = {0.f, 0.f, 0.f, 0.f};
        float a2[4] = {0.f, 0.f, 0.f, 0.f};
        float a3[4] = {0.f, 0.f, 0.f, 0.f};
#pragma unroll
        for (int k = 0; k < 8; ++k) {
            int kb = k * 32;
            uint32_t bh0 = *(const uint32_t*)(Bh + kb);
            uint32_t bh1 = *(const uint32_t*)(Bh + kb + 16);
            uint32_t bl0 = *(const uint32_t*)(Bl + kb);
            uint32_t bl1 = *(const uint32_t*)(Bl + kb + 16);
            mma16816(a1, ahf[k], bh0, bh1);
            mma16816(a2, alf[k], bh0, bh1);
            mma16816(a3, ahf[k], bl0, bl1);
        }
        int v = nc + cq;
        float g0 = ogm[v], g1 = ogm[v + 1], b0 = obt[v], b1 = obt[v + 1];
        if (gi0 < NPTS) {
            float2 r = *(const float2*)(resid + (size_t)gi0 * PL + v);
            *(float2*)(Out + (size_t)gi0 * PL + v) = make_float2(
                fmaxf((a1[0] + (a2[0] + a3[0])) * g0 + b0, 0.f) + r.x,
                fmaxf((a1[1] + (a2[1] + a3[1])) * g1 + b1, 0.f) + r.y);
        }
        if (gi1 < NPTS) {
            float2 r = *(const float2*)(resid + (size_t)gi1 * PL + v);
            *(float2*)(Out + (size_t)gi1 * PL + v) = make_float2(
                fmaxf((a1[2] + (a2[2] + a3[2])) * g0 + b0, 0.f) + r.x,
                fmaxf((a1[3] + (a2[3] + a3[3])) * g1 + b1, 0.f) + r.y);
        }
    }
}

// ================= masked gather of Y + BN/relu + choice ====================
__global__ void k_qg(const int* __restrict__ nidx, const int* __restrict__ nmask,
                     const float* __restrict__ qg, const float* __restrict__ qb,
                     const float* __restrict__ bch) {
    __shared__ float wc[2048];
    __shared__ float bs[128];
    int t = threadIdx.x;
    for (int e = t; e < 2048; e += 256) wc[e] = g_Wc2[e];
    for (int e = t; e < 128; e += 256) bs[e] = bch[e];
    __syncthreads();
    int lane = t & 31, w = t >> 5;
    int i = blockIdx.x * 8 + w;
    if (i >= NPTS) return;
    int v = lane & 15, h = lane >> 4;

    float qp = 0.f;
#pragma unroll
    for (int tt = 0; tt < 14; ++tt) {
        int k = 2 * tt + h;
        bool ok = (k < KOFF);
        int m = ok ? nmask[(size_t)k * NPTS + i] : 0;
        int j = ok ? nidx[(size_t)k * NPTS + i] : 0;
        float val = m ? g_Y[(size_t)j * NQ + k * 16 + v] : 0.f;
        qp += val;
    }
    qp += __shfl_xor_sync(0xffffffffu, qp, 16);
    float qf = fmaxf(qp * qg[v] + qb[v], 0.f);
    float qa[16];
#pragma unroll
    for (int vv = 0; vv < 16; ++vv) qa[vv] = __shfl_sync(0xffffffffu, qf, vv);

    float4 av = ((const float4*)bs)[lane];
#pragma unroll
    for (int vv = 0; vv < 16; ++vv) {
        float4 wv4 = *(const float4*)(wc + vv * 128 + lane * 4);
        av.x += qa[vv] * wv4.x; av.y += qa[vv] * wv4.y;
        av.z += qa[vv] * wv4.z; av.w += qa[vv] * wv4.w;
    }
    float s = fmaxf(av.x, 0.f) + fmaxf(av.y, 0.f) + fmaxf(av.z, 0.f) + fmaxf(av.w, 0.f);
#pragma unroll
    for (int d = 16; d; d >>= 1) s += __shfl_xor_sync(0xffffffffu, s, d);
    if (lane == 0) g_choice[i] = s;
}

// ================= attention (rank-1 scores) + weighted aggregation ==========
__global__ void k_attn(const int* __restrict__ nidx, const int* __restrict__ nmask) {
    int lane = threadIdx.x & 31;
    int wid = threadIdx.x >> 5;
    int i = blockIdx.x * 8 + wid;
    if (i >= NPTS) return;
    float tC = g_C[0] * g_choice[i];
    int m = 0, j = 0;
    float s = -1e9f;
    if (lane < KOFF) {
        m = nmask[(size_t)lane * NPTS + i];
        j = nidx[(size_t)lane * NPTS + i];
        s = m ? tC * g_choice[j] : -1e9f;
    }
    float mx = s;
#pragma unroll
    for (int d = 16; d; d >>= 1) mx = fmaxf(mx, __shfl_xor_sync(0xffffffffu, mx, d));
    float e = (lane < KOFF && m) ? expf(s - mx) : 0.f;
    float se = e;
#pragma unroll
    for (int d = 16; d; d >>= 1) se += __shfl_xor_sync(0xffffffffu, se, d);
    float a = e / se;

    float4 acc = {0.f, 0.f, 0.f, 0.f};
    for (int k = 0; k < KOFF; ++k) {
        float ak = __shfl_sync(0xffffffffu, a, k);
        int jk = __shfl_sync(0xffffffffu, j, k);
        int mk = __shfl_sync(0xffffffffu, m, k);
        if (mk) {
            float4 v = ((const float4*)g_vf)[(size_t)jk * 32 + lane];
            acc.x += ak * v.x; acc.y += ak * v.y; acc.z += ak * v.z; acc.w += ak * v.w;
        }
    }
    ((float4*)g_agg)[(size_t)i * 32 + lane] = acc;
}

// ================= launch ====================================================
extern "C" void kernel_launch(void* const* d_in, const int* in_sizes, int n_in,
                              void* d_out, int out_size) {
    const float* x      = (const float*)d_in[0];
    const float* coords = (const float*)d_in[1];
    const float* Wq     = (const float*)d_in[2];
    const float* qg     = (const float*)d_in[3];
    const float* qb     = (const float*)d_in[4];
    const float* Wv     = (const float*)d_in[5];
    const float* vg     = (const float*)d_in[6];
    const float* vb     = (const float*)d_in[7];
    const float* cb     = (const float*)d_in[8];
    const float* Wch    = (const float*)d_in[9];
    const float* bch    = (const float*)d_in[10];
    const float* Wpos   = (const float*)d_in[11];
    const float* bpos   = (const float*)d_in[12];
    const float* Wo     = (const float*)d_in[13];
    const float* ogm    = (const float*)d_in[14];
    const float* obt    = (const float*)d_in[15];
    const int*   nidx   = (const int*)d_in[16];
    const int*   nmask  = (const int*)d_in[17];
    float* out = (float*)d_out;

    size_t smYV = (size_t)(2 * 128 * KP * 2) + (size_t)(2 * 112 * KP * 2) + 128 * 16 * 4;
    size_t smO  = (size_t)(4 * 128 * KP * 2);
    cudaFuncSetAttribute(k_mmaYV, cudaFuncAttributeMaxDynamicSharedMemorySize, (int)smYV);
    cudaFuncSetAttribute(k_mmaO,  cudaFuncAttributeMaxDynamicSharedMemorySize, (int)smO);

    int mblocks = (NPTS + 127) / 128;  // 782

    k_prep<<<19, 256>>>(cb, Wch, Wq, Wv, Wo);
    k_mmaYV<<<mblocks, 256, smYV>>>(x, vg, vb, coords, Wpos, bpos);
    k_qg<<<(NPTS + 7) / 8, 256>>>(nidx, nmask, qg, qb, bch);
    k_attn<<<(NPTS + 7) / 8, 256>>>(nidx, nmask);
    k_mmaO<<<mblocks, 256, smO>>>(ogm, obt, x, out);
}